// round 5
// baseline (speedup 1.0000x reference)
#include <cuda_runtime.h>
#include <cstdint>

// label: int32 [8,1024,1024]; out: float32 [8,1,64,64]
// One warp = 16-row x 64-col strip = 4 tiles of 16x16 (4 KB).
// Each warp-LDG.128 covers 2 full rows (512 contiguous bytes); 8 LDGs
// front-batched -> MLP=8, one exposed DRAM round-trip per warp.
// Lane L: int4-col (L&15), row parity (L>>4); all 32 values of a lane
// belong to tile (L&15)>>2. Reduce: xor1, xor2 (packed bytes), expand,
// xor16 (halfwords).
#define CTA_THREADS 128

__global__ __launch_bounds__(CTA_THREADS) void DownscaleLabel_kernel(
    const int* __restrict__ label, float* __restrict__ out)
{
    const int w    = threadIdx.x >> 5;   // warp 0..3
    const int lane = threadIdx.x & 31;

    const int blk = blockIdx.x;          // 0..2047
    const int b   = blk >> 8;            // image 0..7
    const int rem = blk & 255;
    const int s   = rem >> 2;            // tile-row strip 0..63
    const int q   = rem & 3;             // 256-col quarter 0..3

    // int4 index within the 256-int4 image row
    const int col4 = (lane & 15);                       // 0..15 within strip
    const int c4   = q * 64 + w * 16 + col4;            // strip base + col
    const int rp   = lane >> 4;                         // row parity 0/1

    const int4* base = reinterpret_cast<const int4*>(label)
                     + (size_t)b * (1024 * 256)
                     + (size_t)(s * 16 + rp) * 256
                     + c4;

    // Front-batched loads: 8 LDG.128, rows rp, rp+2, ..., rp+14.
    int4 v[8];
    #pragma unroll
    for (int r = 0; r < 8; ++r)
        v[r] = __ldg(base + (size_t)(r * 2) * 256);

    // Packed per-lane histogram: lo = classes 0..3 (byte fields), hi = 4..7.
    // Per-lane max per field = 32 -> fits.
    unsigned lo = 0u, hi = 0u;
    #pragma unroll
    for (int r = 0; r < 8; ++r) {
        int vals[4] = { v[r].x, v[r].y, v[r].z, v[r].w };
        #pragma unroll
        for (int j = 0; j < 4; ++j) {
            unsigned c   = (unsigned)vals[j] & 7u;     // -1 -> 7
            unsigned inc = 1u << ((c & 3u) << 3);      // byte-field inc
            if (c < 4u) lo += inc; else hi += inc;
        }
    }

    // Reduce over the 8 lanes sharing a tile: xor1, xor2 in packed bytes
    // (field max 64 then 128, fits 8 bits), then halfwords for xor16.
    lo += __shfl_xor_sync(0xFFFFFFFFu, lo, 1);
    hi += __shfl_xor_sync(0xFFFFFFFFu, hi, 1);
    lo += __shfl_xor_sync(0xFFFFFFFFu, lo, 2);
    hi += __shfl_xor_sync(0xFFFFFFFFu, hi, 2);

    unsigned w0 = lo         & 0x00FF00FFu;   // classes 0, 2
    unsigned w1 = (lo >> 8)  & 0x00FF00FFu;   // classes 1, 3
    unsigned w2 = hi         & 0x00FF00FFu;   // classes 4, 6
    unsigned w3 = (hi >> 8)  & 0x00FF00FFu;   // classes 5, 7

    w0 += __shfl_xor_sync(0xFFFFFFFFu, w0, 16);
    w1 += __shfl_xor_sync(0xFFFFFFFFu, w1, 16);
    w2 += __shfl_xor_sync(0xFFFFFFFFu, w2, 16);
    w3 += __shfl_xor_sync(0xFFFFFFFFu, w3, 16);

    // Writer lanes: lane in {0,4,8,12} -> tile t = lane>>2 (0..3)
    if (lane < 16 && (lane & 3) == 0) {
        int cnt[8];
        cnt[0] = (int)(w0 & 0xFFFFu); cnt[2] = (int)(w0 >> 16);
        cnt[1] = (int)(w1 & 0xFFFFu); cnt[3] = (int)(w1 >> 16);
        cnt[4] = (int)(w2 & 0xFFFFu); cnt[6] = (int)(w2 >> 16);
        cnt[5] = (int)(w3 & 0xFFFFu); cnt[7] = (int)(w3 >> 16);

        int best = cnt[0], bi = 0;
        #pragma unroll
        for (int c = 1; c < 8; ++c)
            if (cnt[c] > best) { best = cnt[c]; bi = c; }

        int res = (bi == 7 || best < 192) ? -1 : bi;   // 192/256 = 0.75 exact

        const int tx = q * 16 + w * 4 + (lane >> 2);   // tile col 0..63
        out[(size_t)b * 4096 + s * 64 + tx] = (float)res;
    }
}

extern "C" void kernel_launch(void* const* d_in, const int* in_sizes, int n_in,
                              void* d_out, int out_size) {
    const int* label = (const int*)d_in[0];
    float* out = (float*)d_out;
    DownscaleLabel_kernel<<<2048, CTA_THREADS>>>(label, out);
}

// round 6
// speedup vs baseline: 1.2316x; 1.2316x over previous
#include <cuda_runtime.h>
#include <cstdint>

// label: int32 [8,1024,1024]; out: float32 [8,1,64,64]
// One warp = 16-row x 64-col strip = 4 tiles of 16x16 (4 KB).
// 8 front-batched LDG.128 per lane-row-pair (launch_bounds(128,8) gives the
// 64-reg budget needed to keep all 8 int4 in flight -> MLP=8).
// Histogram: 64-bit byte-field accumulator, acc += 1<<8*(v&7), branch-free.
#define CTA_THREADS 128

__global__ __launch_bounds__(CTA_THREADS, 8) void DownscaleLabel_kernel(
    const int* __restrict__ label, float* __restrict__ out)
{
    const int w    = threadIdx.x >> 5;   // warp 0..3
    const int lane = threadIdx.x & 31;

    const int blk = blockIdx.x;          // 0..2047
    const int b   = blk >> 8;            // image 0..7
    const int rem = blk & 255;
    const int s   = rem >> 2;            // tile-row strip 0..63
    const int q   = rem & 3;             // 256-col quarter 0..3

    const int col4 = (lane & 15);                  // int4 col within strip
    const int c4   = q * 64 + w * 16 + col4;       // int4 col within row
    const int rp   = lane >> 4;                    // row parity 0/1

    const int4* base = reinterpret_cast<const int4*>(label)
                     + (size_t)b * (1024 * 256)
                     + (size_t)(s * 16 + rp) * 256
                     + c4;

    // Front-batched loads: 8 independent LDG.128 (rows rp, rp+2, ..., rp+14).
    int4 v[8];
    #pragma unroll
    for (int r = 0; r < 8; ++r)
        v[r] = __ldg(base + (size_t)(r * 2) * 256);

    // Branch-free packed histogram: byte field per class in a 64-bit acc.
    // Per-lane max per field = 32 -> fits in 8 bits.
    unsigned long long acc = 0ull;
    #pragma unroll
    for (int r = 0; r < 8; ++r) {
        int vals[4] = { v[r].x, v[r].y, v[r].z, v[r].w };
        #pragma unroll
        for (int j = 0; j < 4; ++j) {
            unsigned t = ((unsigned)vals[j] & 7u) << 3;   // 8 * class
            acc += 1ull << t;
        }
    }

    unsigned lo = (unsigned)acc;          // classes 0..3 (byte fields)
    unsigned hi = (unsigned)(acc >> 32);  // classes 4..7

    // Reduce over the 8 lanes sharing a tile: xor1, xor2 in packed bytes
    // (field max 64 then 128, fits 8 bits), then halfwords for xor16.
    lo += __shfl_xor_sync(0xFFFFFFFFu, lo, 1);
    hi += __shfl_xor_sync(0xFFFFFFFFu, hi, 1);
    lo += __shfl_xor_sync(0xFFFFFFFFu, lo, 2);
    hi += __shfl_xor_sync(0xFFFFFFFFu, hi, 2);

    unsigned w0 = lo         & 0x00FF00FFu;   // classes 0, 2
    unsigned w1 = (lo >> 8)  & 0x00FF00FFu;   // classes 1, 3
    unsigned w2 = hi         & 0x00FF00FFu;   // classes 4, 6
    unsigned w3 = (hi >> 8)  & 0x00FF00FFu;   // classes 5, 7

    w0 += __shfl_xor_sync(0xFFFFFFFFu, w0, 16);
    w1 += __shfl_xor_sync(0xFFFFFFFFu, w1, 16);
    w2 += __shfl_xor_sync(0xFFFFFFFFu, w2, 16);
    w3 += __shfl_xor_sync(0xFFFFFFFFu, w3, 16);

    // Writer lanes: lane in {0,4,8,12} -> tile t = lane>>2 (0..3)
    if (lane < 16 && (lane & 3) == 0) {
        int cnt[8];
        cnt[0] = (int)(w0 & 0xFFFFu); cnt[2] = (int)(w0 >> 16);
        cnt[1] = (int)(w1 & 0xFFFFu); cnt[3] = (int)(w1 >> 16);
        cnt[4] = (int)(w2 & 0xFFFFu); cnt[6] = (int)(w2 >> 16);
        cnt[5] = (int)(w3 & 0xFFFFu); cnt[7] = (int)(w3 >> 16);

        int best = cnt[0], bi = 0;
        #pragma unroll
        for (int c = 1; c < 8; ++c)
            if (cnt[c] > best) { best = cnt[c]; bi = c; }

        int res = (bi == 7 || best < 192) ? -1 : bi;   // 192/256 = 0.75 exact

        const int tx = q * 16 + w * 4 + (lane >> 2);   // tile col 0..63
        out[(size_t)b * 4096 + s * 64 + tx] = (float)res;
    }
}

extern "C" void kernel_launch(void* const* d_in, const int* in_sizes, int n_in,
                              void* d_out, int out_size) {
    const int* label = (const int*)d_in[0];
    float* out = (float*)d_out;
    DownscaleLabel_kernel<<<2048, CTA_THREADS>>>(label, out);
}

// round 7
// speedup vs baseline: 1.2362x; 1.0037x over previous
#include <cuda_runtime.h>
#include <cstdint>

// label: int32 [8,1024,1024]; out: float32 [8,1,64,64]
// Strip = 16 rows x 64 cols = 4 tiles (4 KB). 2048 warps (512 CTAs x 4),
// each warp pipelines 4 strips (stride 2048 strips = +2 images = constant
// address delta). Double-buffered prefetch keeps 8 LDG.128 in flight
// continuously. Single wave (~3.5 CTAs/SM), 128-reg budget.
#define CTA_THREADS 128

__global__ __launch_bounds__(CTA_THREADS, 4) void DownscaleLabel_kernel(
    const int* __restrict__ label, float* __restrict__ out)
{
    const int w    = threadIdx.x >> 5;
    const int lane = threadIdx.x & 31;
    const int g    = blockIdx.x * 4 + w;      // warp id 0..2047 = base strip

    const int b0   = g >> 10;                 // image 0..1 (iter adds 2)
    const int rem  = g & 1023;
    const int s    = rem >> 4;                // tile-row band 0..63
    const int q    = rem & 15;                // 64-col sixteenth 0..15

    const int col4 = lane & 15;               // int4 col within strip
    const int rp   = lane >> 4;               // row parity

    const int4* base = reinterpret_cast<const int4*>(label)
                     + (size_t)b0 * (1024 * 256)
                     + (size_t)(s * 16 + rp) * 256
                     + q * 16 + col4;
    const size_t iterStride = (size_t)2 * 1024 * 256;   // +2 images (int4)

    float* obase = out + (size_t)b0 * 4096 + s * 64 + q * 4;

    int4 buf[2][8];

    // Preload strip 0 (8 coalesced LDG.128, rows rp, rp+2, ..., rp+14)
    #pragma unroll
    for (int r = 0; r < 8; ++r)
        buf[0][r] = __ldg(base + (size_t)(r * 2) * 256);

    #pragma unroll
    for (int it = 0; it < 4; ++it) {
        // Prefetch next strip into the other buffer
        if (it < 3) {
            const int4* p = base + (size_t)(it + 1) * iterStride;
            #pragma unroll
            for (int r = 0; r < 8; ++r)
                buf[(it + 1) & 1][r] = __ldg(p + (size_t)(r * 2) * 256);
        }

        // Branch-free packed histogram of current strip.
        // Per-lane max per byte field = 32.
        unsigned long long acc = 0ull;
        #pragma unroll
        for (int r = 0; r < 8; ++r) {
            int4 v = buf[it & 1][r];
            int vals[4] = { v.x, v.y, v.z, v.w };
            #pragma unroll
            for (int j = 0; j < 4; ++j)
                acc += 1ull << (((unsigned)vals[j] & 7u) << 3);
        }

        unsigned lo = (unsigned)acc;           // classes 0..3
        unsigned hi = (unsigned)(acc >> 32);   // classes 4..7

        // Reduce over 8 lanes per tile: xor1, xor2 packed bytes
        // (max 64 then 128), expand to halfwords, xor16 (max 256).
        lo += __shfl_xor_sync(0xFFFFFFFFu, lo, 1);
        hi += __shfl_xor_sync(0xFFFFFFFFu, hi, 1);
        lo += __shfl_xor_sync(0xFFFFFFFFu, lo, 2);
        hi += __shfl_xor_sync(0xFFFFFFFFu, hi, 2);

        unsigned w0 = lo         & 0x00FF00FFu;   // classes 0, 2
        unsigned w1 = (lo >> 8)  & 0x00FF00FFu;   // classes 1, 3
        unsigned w2 = hi         & 0x00FF00FFu;   // classes 4, 6
        unsigned w3 = (hi >> 8)  & 0x00FF00FFu;   // classes 5, 7

        w0 += __shfl_xor_sync(0xFFFFFFFFu, w0, 16);
        w1 += __shfl_xor_sync(0xFFFFFFFFu, w1, 16);
        w2 += __shfl_xor_sync(0xFFFFFFFFu, w2, 16);
        w3 += __shfl_xor_sync(0xFFFFFFFFu, w3, 16);

        if (lane < 16 && (lane & 3) == 0) {
            int cnt[8];
            cnt[0] = (int)(w0 & 0xFFFFu); cnt[2] = (int)(w0 >> 16);
            cnt[1] = (int)(w1 & 0xFFFFu); cnt[3] = (int)(w1 >> 16);
            cnt[4] = (int)(w2 & 0xFFFFu); cnt[6] = (int)(w2 >> 16);
            cnt[5] = (int)(w3 & 0xFFFFu); cnt[7] = (int)(w3 >> 16);

            int best = cnt[0], bi = 0;
            #pragma unroll
            for (int c = 1; c < 8; ++c)
                if (cnt[c] > best) { best = cnt[c]; bi = c; }

            int res = (bi == 7 || best < 192) ? -1 : bi;   // 192/256 = 0.75

            obase[(size_t)it * 2 * 4096 + (lane >> 2)] = (float)res;
        }
    }
}

extern "C" void kernel_launch(void* const* d_in, const int* in_sizes, int n_in,
                              void* d_out, int out_size) {
    const int* label = (const int*)d_in[0];
    float* out = (float*)d_out;
    DownscaleLabel_kernel<<<512, CTA_THREADS>>>(label, out);
}